// round 2
// baseline (speedup 1.0000x reference)
#include <cuda_runtime.h>
#include <cuda_bf16.h>
#include <math.h>

#define BQ 2
#define TQ 2048
#define DMODEL 1024
#define DINNER 2048
#define NHEADS 32
#define DHEAD 64
#define DSTATE 16
#define DCONV 4
#define PROJ_OUT (2*DINNER + 2*NHEADS + 4*DSTATE)   // 4224
#define BT (BQ*TQ)                                   // 4096
#define PARAM_OFF (2*DINNER)                         // 4096
#define BC_OFF (2*DINNER + 2*NHEADS)                 // 4160

// ---------------- scratch (device globals; no allocation) ----------------
__device__ float g_h1  [BT * DMODEL];
__device__ float g_proj[(size_t)BT * PROJ_OUT];
__device__ float g_val [(size_t)BT * DINNER];
__device__ float g_par [(size_t)BT * NHEADS * 2];   // A, dt
__device__ float g_scan[(size_t)BT * DINNER];
__device__ float g_yg  [(size_t)BT * DINNER];
__device__ float g_x1  [BT * DMODEL];
__device__ float g_h2  [BT * DMODEL];
__device__ float g_ff  [(size_t)BT * 4*DMODEL];

// ---------------- helpers ----------------
__device__ __forceinline__ float sigmoidf_(float x) { return 1.f / (1.f + __expf(-x)); }
__device__ __forceinline__ float siluf_(float x)    { return x / (1.f + __expf(-x)); }
__device__ __forceinline__ float geluf_(float x) {
    float x3 = x * x * x;
    return 0.5f * x * (1.f + tanhf(0.7978845608028654f * (x + 0.044715f * x3)));
}
__device__ __forceinline__ float softplusf_(float x) {
    return (x > 20.f) ? x : log1pf(expf(x));
}

__device__ __forceinline__ float block_reduce_sum(float v) {
    __shared__ float sh[32];
    int lane = threadIdx.x & 31, wid = threadIdx.x >> 5;
    int nwarps = blockDim.x >> 5;
    #pragma unroll
    for (int m = 16; m > 0; m >>= 1) v += __shfl_xor_sync(0xffffffffu, v, m);
    if (lane == 0) sh[wid] = v;
    __syncthreads();
    if (wid == 0) {
        v = (lane < nwarps) ? sh[lane] : 0.f;
        #pragma unroll
        for (int m = 16; m > 0; m >>= 1) v += __shfl_xor_sync(0xffffffffu, v, m);
        if (lane == 0) sh[0] = v;
    }
    __syncthreads();
    return sh[0];
}

// ---------------- rmsnorm: out = x * rsqrt(mean(x^2)+eps) * w ----------------
__global__ void rmsnorm_kernel(const float* __restrict__ x, const float* __restrict__ w,
                               float* __restrict__ out, int D) {
    int row = blockIdx.x;
    const float* xr = x + (size_t)row * D;
    float ss = 0.f;
    for (int i = threadIdx.x; i < D; i += blockDim.x) { float v = xr[i]; ss += v * v; }
    ss = block_reduce_sum(ss);
    float inv = rsqrtf(ss / (float)D + 1e-6f);
    float* orow = out + (size_t)row * D;
    for (int i = threadIdx.x; i < D; i += blockDim.x) orow[i] = xr[i] * inv * w[i];
}

// ---------------- gated rmsnorm: t = scan_y * silu(gate); yg = rmsnorm(t) ----------------
__global__ void gated_norm_kernel(const float* __restrict__ proj, const float* __restrict__ scan_y,
                                  const float* __restrict__ w, float* __restrict__ yg) {
    __shared__ float buf[DINNER];
    int row = blockIdx.x;
    const float* prow = proj + (size_t)row * PROJ_OUT;      // gate at offset 0
    const float* sy = scan_y + (size_t)row * DINNER;
    float ss = 0.f;
    for (int i = threadIdx.x; i < DINNER; i += blockDim.x) {
        float g = prow[i];
        float t = sy[i] * siluf_(g);
        buf[i] = t; ss += t * t;
    }
    ss = block_reduce_sum(ss);
    float inv = rsqrtf(ss / (float)DINNER + 1e-6f);
    float* orow = yg + (size_t)row * DINNER;
    for (int i = threadIdx.x; i < DINNER; i += blockDim.x) orow[i] = buf[i] * inv * w[i];
}

// ---------------- causal depthwise conv + silu ----------------
__global__ void conv_silu_kernel(const float* __restrict__ proj, const float* __restrict__ conv_w,
                                 const float* __restrict__ conv_b, float* __restrict__ value) {
    int idx = blockIdx.x * blockDim.x + threadIdx.x;
    if (idx >= BT * DINNER) return;
    int c = idx & (DINNER - 1);
    int bt = idx >> 11;
    int t = bt & (TQ - 1);
    int b = bt >> 11;
    float acc = conv_b[c];
    #pragma unroll
    for (int k = 0; k < DCONV; ++k) {
        int ts = t - (DCONV - 1) + k;
        if (ts >= 0)
            acc += proj[(size_t)(b * TQ + ts) * PROJ_OUT + DINNER + c] * conv_w[c * DCONV + k];
    }
    value[(size_t)idx] = siluf_(acc);
}

// ---------------- precompute A=softplus(p0), dt=sigmoid(p1) ----------------
__global__ void params_kernel(const float* __restrict__ proj, float* __restrict__ par) {
    int idx = blockIdx.x * blockDim.x + threadIdx.x;    // over BT*NHEADS
    if (idx >= BT * NHEADS) return;
    int h = idx & (NHEADS - 1);
    int bt = idx >> 5;
    const float* prow = proj + (size_t)bt * PROJ_OUT + PARAM_OFF;
    par[idx * 2 + 0] = softplusf_(prow[2 * h]);
    par[idx * 2 + 1] = sigmoidf_(prow[2 * h + 1]);
}

// ---------------- sequential SSM scan ----------------
// grid: 128 blocks = (b,h,half_of_p); block: 512 threads = 32 p x 16 n
__global__ void scan_kernel(const float* __restrict__ proj, const float* __restrict__ par,
                            const float* __restrict__ value, float* __restrict__ scan_y) {
    int blk = blockIdx.x;
    int bh = blk >> 1;
    int b = bh >> 5;
    int h = bh & 31;
    int half = blk & 1;
    int tid = threadIdx.x;
    int p = half * 32 + (tid >> 4);
    int n = tid & 15;
    float S0 = 0.f, S1 = 0.f;
    const size_t rowbase = (size_t)b * TQ;
    for (int t = 0; t < TQ; ++t) {
        size_t row = rowbase + t;
        const float* prow = proj + row * PROJ_OUT + BC_OFF;
        float A  = par[(row * NHEADS + h) * 2 + 0];
        float dt = par[(row * NHEADS + h) * 2 + 1];
        float B0 = prow[n];
        float B1 = prow[16 + n];
        float C0 = prow[32 + n];
        float C1 = prow[48 + n];
        float u  = value[row * DINNER + h * DHEAD + p];
        float dtA = dt * A;
        float du = dt * u;
        float s0n = fmaf(-dtA, S1, fmaf(B0, du, S0));
        float s1n = fmaf(dt, S0, fmaf(1.f - dt * dtA, S1, dt * B1 * du));
        S0 = s0n; S1 = s1n;
        float y = C0 * s0n + C1 * s1n;
        y += __shfl_xor_sync(0xffffffffu, y, 8);
        y += __shfl_xor_sync(0xffffffffu, y, 4);
        y += __shfl_xor_sync(0xffffffffu, y, 2);
        y += __shfl_xor_sync(0xffffffffu, y, 1);
        if (n == 0) scan_y[row * DINNER + h * DHEAD + p] = y;
    }
}

// ---------------- SGEMM: C[M,N] = act(A[M,K] @ W[N,K]^T + bias) + res ----------------
// 128x128 tile, BK=8, 256 threads, 8x8 per thread (4+4 split fragments)
__global__ void __launch_bounds__(256, 2)
sgemm_kernel(const float* __restrict__ A, const float* __restrict__ W,
             const float* __restrict__ bias, const float* __restrict__ res,
             float* __restrict__ C, int M, int N, int K, int act) {
    __shared__ float As[8][128];
    __shared__ float Bs[8][128];
    int tid = threadIdx.x;
    int row0 = blockIdx.y * 128, col0 = blockIdx.x * 128;
    int ld_r = tid >> 1;
    int ld_c = (tid & 1) * 4;
    const float* Ap = A + (size_t)(row0 + ld_r) * K + ld_c;
    const float* Wp = W + (size_t)(col0 + ld_r) * K + ld_c;
    int tx = tid & 15, ty = tid >> 4;
    int rA = ty * 4, cB = tx * 4;
    float acc[8][8];
    #pragma unroll
    for (int i = 0; i < 8; ++i)
        #pragma unroll
        for (int j = 0; j < 8; ++j) acc[i][j] = 0.f;

    for (int k0 = 0; k0 < K; k0 += 8) {
        float4 av = *(const float4*)(Ap + k0);
        float4 wv = *(const float4*)(Wp + k0);
        As[ld_c + 0][ld_r] = av.x; As[ld_c + 1][ld_r] = av.y;
        As[ld_c + 2][ld_r] = av.z; As[ld_c + 3][ld_r] = av.w;
        Bs[ld_c + 0][ld_r] = wv.x; Bs[ld_c + 1][ld_r] = wv.y;
        Bs[ld_c + 2][ld_r] = wv.z; Bs[ld_c + 3][ld_r] = wv.w;
        __syncthreads();
        #pragma unroll
        for (int k = 0; k < 8; ++k) {
            float a[8], b[8];
            *(float4*)&a[0] = *(const float4*)&As[k][rA];
            *(float4*)&a[4] = *(const float4*)&As[k][rA + 64];
            *(float4*)&b[0] = *(const float4*)&Bs[k][cB];
            *(float4*)&b[4] = *(const float4*)&Bs[k][cB + 64];
            #pragma unroll
            for (int i = 0; i < 8; ++i)
                #pragma unroll
                for (int j = 0; j < 8; ++j)
                    acc[i][j] = fmaf(a[i], b[j], acc[i][j]);
        }
        __syncthreads();
    }

    #pragma unroll
    for (int i = 0; i < 8; ++i) {
        int gr = row0 + rA + (i & 3) + ((i >= 4) ? 64 : 0);
        #pragma unroll
        for (int jg = 0; jg < 2; ++jg) {
            int gc = col0 + cB + jg * 64;
            float4 v;
            v.x = acc[i][jg * 4 + 0]; v.y = acc[i][jg * 4 + 1];
            v.z = acc[i][jg * 4 + 2]; v.w = acc[i][jg * 4 + 3];
            if (bias) {
                v.x += bias[gc + 0]; v.y += bias[gc + 1];
                v.z += bias[gc + 2]; v.w += bias[gc + 3];
            }
            if (act == 1) {
                v.x = geluf_(v.x); v.y = geluf_(v.y);
                v.z = geluf_(v.z); v.w = geluf_(v.w);
            }
            if (res) {
                const float* rp = res + (size_t)gr * N + gc;
                v.x += rp[0]; v.y += rp[1]; v.z += rp[2]; v.w += rp[3];
            }
            *(float4*)(C + (size_t)gr * N + gc) = v;
        }
    }
}

// ---------------- launch ----------------
extern "C" void kernel_launch(void* const* d_in, const int* in_sizes, int n_in,
                              void* d_out, int out_size) {
    const float* x        = (const float*)d_in[0];
    const float* w_in     = (const float*)d_in[1];
    const float* conv_w   = (const float*)d_in[2];
    const float* conv_b   = (const float*)d_in[3];
    const float* norm1_w  = (const float*)d_in[4];
    const float* out_nw   = (const float*)d_in[5];
    const float* w_out    = (const float*)d_in[6];
    const float* norm2_w  = (const float*)d_in[7];
    const float* ff_w1    = (const float*)d_in[8];
    const float* ff_b1    = (const float*)d_in[9];
    const float* ff_w2    = (const float*)d_in[10];
    const float* ff_b2    = (const float*)d_in[11];
    float* out = (float*)d_out;

    float *h1, *proj, *val, *par, *scan, *yg, *x1, *h2, *ff;
    cudaGetSymbolAddress((void**)&h1,   g_h1);
    cudaGetSymbolAddress((void**)&proj, g_proj);
    cudaGetSymbolAddress((void**)&val,  g_val);
    cudaGetSymbolAddress((void**)&par,  g_par);
    cudaGetSymbolAddress((void**)&scan, g_scan);
    cudaGetSymbolAddress((void**)&yg,   g_yg);
    cudaGetSymbolAddress((void**)&x1,   g_x1);
    cudaGetSymbolAddress((void**)&h2,   g_h2);
    cudaGetSymbolAddress((void**)&ff,   g_ff);

    // 1. h1 = rmsnorm(x, norm1_w)
    rmsnorm_kernel<<<BT, 256>>>(x, norm1_w, h1, DMODEL);
    // 2. proj = h1 @ w_in^T   (4096 x 4224 x 1024)
    sgemm_kernel<<<dim3(PROJ_OUT / 128, BT / 128), 256>>>(h1, w_in, nullptr, nullptr, proj, BT, PROJ_OUT, DMODEL, 0);
    // 3. value = silu(causal_conv(vraw))
    conv_silu_kernel<<<(BT * DINNER + 255) / 256, 256>>>(proj, conv_w, conv_b, val);
    // 4. A/dt precompute
    params_kernel<<<(BT * NHEADS + 255) / 256, 256>>>(proj, par);
    // 5. SSM scan
    scan_kernel<<<2 * BQ * NHEADS, 512>>>(proj, par, val, scan);
    // 6. yg = rmsnorm(scan * silu(gate))
    gated_norm_kernel<<<BT, 256>>>(proj, scan, out_nw, yg);
    // 7. x1 = x + yg @ w_out^T   (4096 x 1024 x 2048)
    sgemm_kernel<<<dim3(DMODEL / 128, BT / 128), 256>>>(yg, w_out, nullptr, x, x1, BT, DMODEL, DINNER, 0);
    // 8. h2 = rmsnorm(x1, norm2_w)
    rmsnorm_kernel<<<BT, 256>>>(x1, norm2_w, h2, DMODEL);
    // 9. ff = gelu(h2 @ ff_w1^T + b1)   (4096 x 4096 x 1024)
    sgemm_kernel<<<dim3(4 * DMODEL / 128, BT / 128), 256>>>(h2, ff_w1, ff_b1, nullptr, ff, BT, 4 * DMODEL, DMODEL, 1);
    // 10. out = x1 + ff @ ff_w2^T + b2   (4096 x 1024 x 4096)
    sgemm_kernel<<<dim3(DMODEL / 128, BT / 128), 256>>>(ff, ff_w2, ff_b2, x1, out, BT, DMODEL, 4 * DMODEL, 0);
}

// round 5
// speedup vs baseline: 1.7471x; 1.7471x over previous
#include <cuda_runtime.h>
#include <cuda_bf16.h>
#include <math.h>
#include <stdint.h>

typedef __nv_bfloat16 bf16;

#define BQ 2
#define TQ 2048
#define DMODEL 1024
#define DINNER 2048
#define NHEADS 32
#define DHEAD 64
#define DCONV 4
#define PROJ_OUT 4224
#define BT 4096
#define PARAM_OFF 4096
#define BC_OFF 4160
#define DFF 4096

// ---------------- scratch (device globals; no allocation) ----------------
__device__ float g_proj[(size_t)BT * PROJ_OUT];
__device__ float g_val [(size_t)BT * DINNER];
__device__ float g_par [(size_t)BT * NHEADS * 2];
__device__ float g_scan[(size_t)BT * DINNER];
__device__ float g_x1  [BT * DMODEL];
__device__ bf16 g_h1h[BT * DMODEL],         g_h1l[BT * DMODEL];
__device__ bf16 g_ygh[(size_t)BT * DINNER], g_ygl[(size_t)BT * DINNER];
__device__ bf16 g_h2h[BT * DMODEL],         g_h2l[BT * DMODEL];
__device__ bf16 g_ffh[(size_t)BT * DFF],    g_ffl[(size_t)BT * DFF];
__device__ bf16 g_winh[PROJ_OUT * 1024],    g_winl[PROJ_OUT * 1024];
__device__ bf16 g_woh [1024 * 2048],        g_wol [1024 * 2048];
__device__ bf16 g_w1h [4096 * 1024],        g_w1l [4096 * 1024];
__device__ bf16 g_w2h [1024 * 4096],        g_w2l [1024 * 4096];

// ---------------- math helpers ----------------
__device__ __forceinline__ float sigmoidf_(float x) { return 1.f / (1.f + __expf(-x)); }
__device__ __forceinline__ float siluf_(float x)    { return x / (1.f + __expf(-x)); }
__device__ __forceinline__ float geluf_(float x) {
    float x3 = x * x * x;
    return 0.5f * x * (1.f + tanhf(0.7978845608028654f * (x + 0.044715f * x3)));
}
__device__ __forceinline__ float softplusf_(float x) {
    return (x > 20.f) ? x : log1pf(expf(x));
}

__device__ __forceinline__ float block_reduce_sum(float v) {
    __shared__ float sh[32];
    int lane = threadIdx.x & 31, wid = threadIdx.x >> 5;
    int nwarps = blockDim.x >> 5;
    #pragma unroll
    for (int m = 16; m > 0; m >>= 1) v += __shfl_xor_sync(0xffffffffu, v, m);
    if (lane == 0) sh[wid] = v;
    __syncthreads();
    if (wid == 0) {
        v = (lane < nwarps) ? sh[lane] : 0.f;
        #pragma unroll
        for (int m = 16; m > 0; m >>= 1) v += __shfl_xor_sync(0xffffffffu, v, m);
        if (lane == 0) sh[0] = v;
    }
    __syncthreads();
    return sh[0];
}

// ---------------- low-level (sm_80-compatible only) ----------------
__device__ __forceinline__ uint32_t smem_u32(const void* p) {
    uint32_t a;
    asm("{ .reg .u64 t; cvta.to.shared.u64 t, %1; cvt.u32.u64 %0, t; }" : "=r"(a) : "l"(p));
    return a;
}
#define CP_ASYNC16(dst, src) \
    asm volatile("cp.async.cg.shared.global [%0], [%1], 16;" :: "r"((uint32_t)(dst)), "l"(src))
#define CP_COMMIT() asm volatile("cp.async.commit_group;" ::: "memory")

__device__ __forceinline__ void ldsm_x4(uint32_t* r, uint32_t addr) {
    asm volatile("ldmatrix.sync.aligned.m8n8.x4.shared.b16 {%0,%1,%2,%3}, [%4];"
                 : "=r"(r[0]), "=r"(r[1]), "=r"(r[2]), "=r"(r[3]) : "r"(addr));
}
// NON-trans x2: W[N,K] row-major IS B col-major for mma.row.col
__device__ __forceinline__ void ldsm_x2(uint32_t* r, uint32_t addr) {
    asm volatile("ldmatrix.sync.aligned.m8n8.x2.shared.b16 {%0,%1}, [%2];"
                 : "=r"(r[0]), "=r"(r[1]) : "r"(addr));
}
__device__ __forceinline__ void mma16816(float* c, const uint32_t* a, const uint32_t* b) {
    asm volatile("mma.sync.aligned.m16n8k16.row.col.f32.bf16.bf16.f32 "
                 "{%0,%1,%2,%3}, {%4,%5,%6,%7}, {%8,%9}, {%0,%1,%2,%3};"
                 : "+f"(c[0]), "+f"(c[1]), "+f"(c[2]), "+f"(c[3])
                 : "r"(a[0]), "r"(a[1]), "r"(a[2]), "r"(a[3]), "r"(b[0]), "r"(b[1]));
}

// ---------------- rmsnorm + bf16 split ----------------
__global__ void rmsnorm_split_kernel(const float* __restrict__ x, const float* __restrict__ w,
                                     bf16* __restrict__ oh, bf16* __restrict__ ol, int D) {
    int row = blockIdx.x;
    const float* xr = x + (size_t)row * D;
    float ss = 0.f;
    for (int i = threadIdx.x; i < D; i += blockDim.x) { float v = xr[i]; ss += v * v; }
    ss = block_reduce_sum(ss);
    float inv = rsqrtf(ss / (float)D + 1e-6f);
    for (int i = threadIdx.x; i < D; i += blockDim.x) {
        float v = xr[i] * inv * w[i];
        bf16 h = __float2bfloat16(v);
        oh[(size_t)row * D + i] = h;
        ol[(size_t)row * D + i] = __float2bfloat16(v - __bfloat162float(h));
    }
}

// ---------------- gated rmsnorm + split ----------------
__global__ void gated_norm_split_kernel(const float* __restrict__ proj, const float* __restrict__ scan_y,
                                        const float* __restrict__ w,
                                        bf16* __restrict__ oh, bf16* __restrict__ ol) {
    __shared__ float buf[DINNER];
    int row = blockIdx.x;
    const float* prow = proj + (size_t)row * PROJ_OUT;
    const float* sy = scan_y + (size_t)row * DINNER;
    float ss = 0.f;
    for (int i = threadIdx.x; i < DINNER; i += blockDim.x) {
        float t = sy[i] * siluf_(prow[i]);
        buf[i] = t; ss += t * t;
    }
    ss = block_reduce_sum(ss);
    float inv = rsqrtf(ss / (float)DINNER + 1e-6f);
    for (int i = threadIdx.x; i < DINNER; i += blockDim.x) {
        float v = buf[i] * inv * w[i];
        bf16 h = __float2bfloat16(v);
        oh[(size_t)row * DINNER + i] = h;
        ol[(size_t)row * DINNER + i] = __float2bfloat16(v - __bfloat162float(h));
    }
}

// ---------------- fp32 -> bf16 hi/lo split (weights) ----------------
__global__ void split_kernel(const float* __restrict__ src, bf16* __restrict__ hi,
                             bf16* __restrict__ lo, int n) {
    int i = blockIdx.x * blockDim.x + threadIdx.x;
    if (i >= n) return;
    float v = src[i];
    bf16 h = __float2bfloat16(v);
    hi[i] = h;
    lo[i] = __float2bfloat16(v - __bfloat162float(h));
}

// ---------------- causal depthwise conv + silu ----------------
__global__ void conv_silu_kernel(const float* __restrict__ proj, const float* __restrict__ conv_w,
                                 const float* __restrict__ conv_b, float* __restrict__ value) {
    int idx = blockIdx.x * blockDim.x + threadIdx.x;
    if (idx >= BT * DINNER) return;
    int c = idx & (DINNER - 1);
    int bt = idx >> 11;
    int t = bt & (TQ - 1);
    int b = bt >> 11;
    float acc = conv_b[c];
    #pragma unroll
    for (int k = 0; k < DCONV; ++k) {
        int ts = t - (DCONV - 1) + k;
        if (ts >= 0)
            acc += proj[(size_t)(b * TQ + ts) * PROJ_OUT + DINNER + c] * conv_w[c * DCONV + k];
    }
    value[(size_t)idx] = siluf_(acc);
}

// ---------------- A/dt precompute ----------------
__global__ void params_kernel(const float* __restrict__ proj, float* __restrict__ par) {
    int idx = blockIdx.x * blockDim.x + threadIdx.x;
    if (idx >= BT * NHEADS) return;
    int h = idx & (NHEADS - 1);
    int bt = idx >> 5;
    const float* prow = proj + (size_t)bt * PROJ_OUT + PARAM_OFF;
    par[idx * 2 + 0] = softplusf_(prow[2 * h]);
    par[idx * 2 + 1] = sigmoidf_(prow[2 * h + 1]);
}

// ---------------- sequential SSM scan (software-pipelined loads) ----------------
__global__ void scan_kernel(const float* __restrict__ proj, const float* __restrict__ par,
                            const float* __restrict__ value, float* __restrict__ scan_y) {
    int blk = blockIdx.x;
    int bh = blk >> 1;
    int b = bh >> 5;
    int h = bh & 31;
    int half = blk & 1;
    int tid = threadIdx.x;
    int p = half * 32 + (tid >> 4);
    int n = tid & 15;
    float S0 = 0.f, S1 = 0.f;
    const size_t rowbase = (size_t)b * TQ;
    const float* pr0 = proj + rowbase * PROJ_OUT + BC_OFF;
    float nA  = par[(rowbase * NHEADS + h) * 2 + 0];
    float ndt = par[(rowbase * NHEADS + h) * 2 + 1];
    float nB0 = pr0[n], nB1 = pr0[16 + n], nC0 = pr0[32 + n], nC1 = pr0[48 + n];
    float nu  = value[rowbase * DINNER + h * DHEAD + p];
    for (int t = 0; t < TQ; ++t) {
        float A = nA, dt = ndt, B0 = nB0, B1 = nB1, C0 = nC0, C1 = nC1, u = nu;
        if (t + 1 < TQ) {
            size_t r2 = rowbase + t + 1;
            const float* p2 = proj + r2 * PROJ_OUT + BC_OFF;
            nA  = par[(r2 * NHEADS + h) * 2 + 0];
            ndt = par[(r2 * NHEADS + h) * 2 + 1];
            nB0 = p2[n]; nB1 = p2[16 + n]; nC0 = p2[32 + n]; nC1 = p2[48 + n];
            nu  = value[r2 * DINNER + h * DHEAD + p];
        }
        float dtA = dt * A;
        float du = dt * u;
        float s0n = fmaf(-dtA, S1, fmaf(B0, du, S0));
        float s1n = fmaf(dt, S0, fmaf(1.f - dt * dtA, S1, dt * B1 * du));
        S0 = s0n; S1 = s1n;
        float y = C0 * s0n + C1 * s1n;
        y += __shfl_xor_sync(0xffffffffu, y, 8);
        y += __shfl_xor_sync(0xffffffffu, y, 4);
        y += __shfl_xor_sync(0xffffffffu, y, 2);
        y += __shfl_xor_sync(0xffffffffu, y, 1);
        if (n == 0) scan_y[(rowbase + t) * DINNER + h * DHEAD + p] = y;
    }
}

// ---------------- bf16 split-precision GEMM via mma.sync (HMMA) ----------------
// C[M,N] = A[M,K] @ W[N,K]^T in ~fp32 precision: Ah*Bh + Ah*Bl + Al*Bh.
// CTA tile 128x128, BK=32, 256 threads (8 warps, 64x32 each), cp.async double buffer.
// mode 0: C = acc ; mode 1: C = acc + bias? + res? ; mode 2: split(gelu(acc+bias)) -> Oh/Ol
#define ASTRIDE 40   // bf16 elems per smem row (80B) -> conflict-free ldmatrix
__global__ void __launch_bounds__(256, 2)
gemm_mma(const bf16* __restrict__ Ah, const bf16* __restrict__ Al,
         const bf16* __restrict__ Bh, const bf16* __restrict__ Bl,
         const float* __restrict__ bias, const float* __restrict__ res,
         float* __restrict__ C, bf16* __restrict__ Oh, bf16* __restrict__ Ol,
         int N, int K, int mode) {
    __shared__ __align__(16) bf16 sA[2][128 * ASTRIDE];
    __shared__ __align__(16) bf16 sB[2][128 * ASTRIDE];
    const int tid = threadIdx.x, wid = tid >> 5, lane = tid & 31;
    const int row0 = blockIdx.y * 128, col0 = blockIdx.x * 128;
    const int wm = wid & 1, wn = wid >> 1;          // 2 x 4 warp grid
    const int kpp = K >> 5;                         // chunks per phase
    const int nch = 3 * kpp;

    const uint32_t sA0 = smem_u32(&sA[0][0]);
    const uint32_t sB0 = smem_u32(&sB[0][0]);
    const uint32_t BUFB = 128 * ASTRIDE * 2;        // bytes per buffer

    float acc[4][4][4];
    #pragma unroll
    for (int mt = 0; mt < 4; ++mt)
        #pragma unroll
        for (int nt = 0; nt < 4; ++nt)
            #pragma unroll
            for (int q = 0; q < 4; ++q) acc[mt][nt][q] = 0.f;

    // loader indices: 512 16B-chunks per tile; thread does s=tid, tid+256
    const int lr0 = tid >> 2, lc0 = tid & 3;
    const int lr1 = lr0 + 64, lc1 = lc0;

    // prefetch chunk 0 (phase 0: Ah, Bh)
    {
        uint32_t da = sA0, db = sB0;
        CP_ASYNC16(da + lr0 * 80 + lc0 * 16, Ah + (size_t)(row0 + lr0) * K + lc0 * 8);
        CP_ASYNC16(da + lr1 * 80 + lc1 * 16, Ah + (size_t)(row0 + lr1) * K + lc1 * 8);
        CP_ASYNC16(db + lr0 * 80 + lc0 * 16, Bh + (size_t)(col0 + lr0) * K + lc0 * 8);
        CP_ASYNC16(db + lr1 * 80 + lc1 * 16, Bh + (size_t)(col0 + lr1) * K + lc1 * 8);
        CP_COMMIT();
    }

    // ldmatrix address components (within a buffer)
    const uint32_t a_row = (uint32_t)(wm * 64 + (lane & 15));
    const uint32_t a_coff = (uint32_t)((lane >> 4) * 8);
    const uint32_t b_row = (uint32_t)(wn * 32 + (lane & 7));
    const uint32_t b_coff = (uint32_t)(((lane >> 3) & 1) * 8);

    for (int ch = 0; ch < nch; ++ch) {
        const int buf = ch & 1;
        if (ch + 1 < nch) {
            const int c2 = ch + 1;
            const int ph = (c2 >= 2 * kpp) ? 2 : ((c2 >= kpp) ? 1 : 0);
            const int k0 = (c2 - ph * kpp) << 5;
            const bf16* pa = (ph == 2) ? Al : Ah;
            const bf16* pb = (ph == 1) ? Bl : Bh;
            uint32_t da = sA0 + (buf ^ 1) * BUFB, db = sB0 + (buf ^ 1) * BUFB;
            CP_ASYNC16(da + lr0 * 80 + lc0 * 16, pa + (size_t)(row0 + lr0) * K + k0 + lc0 * 8);
            CP_ASYNC16(da + lr1 * 80 + lc1 * 16, pa + (size_t)(row0 + lr1) * K + k0 + lc1 * 8);
            CP_ASYNC16(db + lr0 * 80 + lc0 * 16, pb + (size_t)(col0 + lr0) * K + k0 + lc0 * 8);
            CP_ASYNC16(db + lr1 * 80 + lc1 * 16, pb + (size_t)(col0 + lr1) * K + k0 + lc1 * 8);
            CP_COMMIT();
            asm volatile("cp.async.wait_group 1;" ::: "memory");
        } else {
            asm volatile("cp.async.wait_group 0;" ::: "memory");
        }
        __syncthreads();

        const uint32_t ab = sA0 + buf * BUFB;
        const uint32_t bb = sB0 + buf * BUFB;
        #pragma unroll
        for (int ks = 0; ks < 2; ++ks) {
            uint32_t afr[4][4], bfr[4][2];
            #pragma unroll
            for (int mt = 0; mt < 4; ++mt)
                ldsm_x4(afr[mt], ab + (a_row + mt * 16) * 80 + (ks * 16 + a_coff) * 2);
            #pragma unroll
            for (int nt = 0; nt < 4; ++nt)
                ldsm_x2(bfr[nt], bb + (b_row + nt * 8) * 80 + (ks * 16 + b_coff) * 2);
            #pragma unroll
            for (int mt = 0; mt < 4; ++mt)
                #pragma unroll
                for (int nt = 0; nt < 4; ++nt)
                    mma16816(acc[mt][nt], afr[mt], bfr[nt]);
        }
        __syncthreads();
    }

    // epilogue
    const int er = lane >> 2, ec = (lane & 3) << 1;
    #pragma unroll
    for (int mt = 0; mt < 4; ++mt) {
        #pragma unroll
        for (int nt = 0; nt < 4; ++nt) {
            int gr = row0 + wm * 64 + mt * 16 + er;
            int gc = col0 + wn * 32 + nt * 8 + ec;
            const float* cc = acc[mt][nt];
            #pragma unroll
            for (int half = 0; half < 2; ++half) {
                int r = gr + half * 8;
                float v0 = cc[half * 2 + 0], v1 = cc[half * 2 + 1];
                if (mode == 2) {
                    v0 = geluf_(v0 + bias[gc]);
                    v1 = geluf_(v1 + bias[gc + 1]);
                    bf16 h0 = __float2bfloat16(v0), h1 = __float2bfloat16(v1);
                    size_t o = (size_t)r * N + gc;
                    Oh[o] = h0; Oh[o + 1] = h1;
                    Ol[o] = __float2bfloat16(v0 - __bfloat162float(h0));
                    Ol[o + 1] = __float2bfloat16(v1 - __bfloat162float(h1));
                } else {
                    if (bias) { v0 += bias[gc]; v1 += bias[gc + 1]; }
                    if (res) {
                        const float* rp = res + (size_t)r * N + gc;
                        v0 += rp[0]; v1 += rp[1];
                    }
                    float2 v; v.x = v0; v.y = v1;
                    *(float2*)(C + (size_t)r * N + gc) = v;
                }
            }
        }
    }
}

// ---------------- launch ----------------
extern "C" void kernel_launch(void* const* d_in, const int* in_sizes, int n_in,
                              void* d_out, int out_size) {
    const float* x       = (const float*)d_in[0];
    const float* w_in    = (const float*)d_in[1];
    const float* conv_w  = (const float*)d_in[2];
    const float* conv_b  = (const float*)d_in[3];
    const float* norm1_w = (const float*)d_in[4];
    const float* out_nw  = (const float*)d_in[5];
    const float* w_out   = (const float*)d_in[6];
    const float* norm2_w = (const float*)d_in[7];
    const float* ff_w1   = (const float*)d_in[8];
    const float* ff_b1   = (const float*)d_in[9];
    const float* ff_w2   = (const float*)d_in[10];
    const float* ff_b2   = (const float*)d_in[11];
    float* out = (float*)d_out;

    float *proj, *val, *par, *scan, *x1;
    bf16 *h1h, *h1l, *ygh, *ygl, *h2h, *h2l, *ffh, *ffl;
    bf16 *winh, *winl, *woh, *wol, *w1h, *w1l, *w2h, *w2l;
    cudaGetSymbolAddress((void**)&proj, g_proj);
    cudaGetSymbolAddress((void**)&val,  g_val);
    cudaGetSymbolAddress((void**)&par,  g_par);
    cudaGetSymbolAddress((void**)&scan, g_scan);
    cudaGetSymbolAddress((void**)&x1,   g_x1);
    cudaGetSymbolAddress((void**)&h1h,  g_h1h);  cudaGetSymbolAddress((void**)&h1l, g_h1l);
    cudaGetSymbolAddress((void**)&ygh,  g_ygh);  cudaGetSymbolAddress((void**)&ygl, g_ygl);
    cudaGetSymbolAddress((void**)&h2h,  g_h2h);  cudaGetSymbolAddress((void**)&h2l, g_h2l);
    cudaGetSymbolAddress((void**)&ffh,  g_ffh);  cudaGetSymbolAddress((void**)&ffl, g_ffl);
    cudaGetSymbolAddress((void**)&winh, g_winh); cudaGetSymbolAddress((void**)&winl, g_winl);
    cudaGetSymbolAddress((void**)&woh,  g_woh);  cudaGetSymbolAddress((void**)&wol, g_wol);
    cudaGetSymbolAddress((void**)&w1h,  g_w1h);  cudaGetSymbolAddress((void**)&w1l, g_w1l);
    cudaGetSymbolAddress((void**)&w2h,  g_w2h);  cudaGetSymbolAddress((void**)&w2l, g_w2l);

    // weight splits (idempotent)
    split_kernel<<<(PROJ_OUT * 1024 + 255) / 256, 256>>>(w_in, winh, winl, PROJ_OUT * 1024);
    split_kernel<<<(1024 * 2048 + 255) / 256, 256>>>(w_out, woh, wol, 1024 * 2048);
    split_kernel<<<(4096 * 1024 + 255) / 256, 256>>>(ff_w1, w1h, w1l, 4096 * 1024);
    split_kernel<<<(1024 * 4096 + 255) / 256, 256>>>(ff_w2, w2h, w2l, 1024 * 4096);

    // 1. h1 = rmsnorm(x) (split)
    rmsnorm_split_kernel<<<BT, 256>>>(x, norm1_w, h1h, h1l, DMODEL);
    // 2. proj = h1 @ w_in^T  (4096 x 4224 x 1024)
    gemm_mma<<<dim3(PROJ_OUT / 128, BT / 128), 256>>>(h1h, h1l, winh, winl, nullptr, nullptr,
                                                      proj, nullptr, nullptr, PROJ_OUT, DMODEL, 0);
    // 3. conv + silu
    conv_silu_kernel<<<(BT * DINNER + 255) / 256, 256>>>(proj, conv_w, conv_b, val);
    // 4. A/dt
    params_kernel<<<(BT * NHEADS + 255) / 256, 256>>>(proj, par);
    // 5. scan
    scan_kernel<<<2 * BQ * NHEADS, 512>>>(proj, par, val, scan);
    // 6. yg = rmsnorm(scan * silu(gate)) (split)
    gated_norm_split_kernel<<<BT, 256>>>(proj, scan, out_nw, ygh, ygl);
    // 7. x1 = x + yg @ w_out^T  (4096 x 1024 x 2048)
    gemm_mma<<<dim3(DMODEL / 128, BT / 128), 256>>>(ygh, ygl, woh, wol, nullptr, x,
                                                    x1, nullptr, nullptr, DMODEL, DINNER, 1);
    // 8. h2 = rmsnorm(x1) (split)
    rmsnorm_split_kernel<<<BT, 256>>>(x1, norm2_w, h2h, h2l, DMODEL);
    // 9. ffa = split(gelu(h2 @ ff_w1^T + b1))  (4096 x 4096 x 1024)
    gemm_mma<<<dim3(DFF / 128, BT / 128), 256>>>(h2h, h2l, w1h, w1l, ff_b1, nullptr,
                                                 nullptr, ffh, ffl, DFF, DMODEL, 2);
    // 10. out = x1 + ffa @ ff_w2^T + b2  (4096 x 1024 x 4096)
    gemm_mma<<<dim3(DMODEL / 128, BT / 128), 256>>>(ffh, ffl, w2h, w2l, ff_b2, x1,
                                                    out, nullptr, nullptr, DMODEL, DFF, 1);
}

// round 6
// speedup vs baseline: 2.1918x; 1.2545x over previous
#include <cuda_runtime.h>
#include <cuda_bf16.h>
#include <math.h>
#include <stdint.h>

typedef __nv_bfloat16 bf16;

#define BQ 2
#define TQ 2048
#define DMODEL 1024
#define DINNER 2048
#define NHEADS 32
#define DHEAD 64
#define DCONV 4
#define PROJ_OUT 4224
#define BT 4096
#define PARAM_OFF 4096
#define BC_OFF 4160
#define DFF 4096

// ---------------- scratch (device globals; no allocation) ----------------
__device__ float g_proj[(size_t)BT * PROJ_OUT];
__device__ float g_val [(size_t)BT * DINNER];
__device__ float g_par [(size_t)BT * NHEADS * 2];
__device__ float g_bcT [(size_t)BT * 64];          // packed (B0,B1,C0,C1) x 16n
__device__ float g_scan[(size_t)BT * DINNER];
__device__ float g_x1  [BT * DMODEL];
__device__ bf16 g_h1h[BT * DMODEL],         g_h1l[BT * DMODEL];
__device__ bf16 g_ygh[(size_t)BT * DINNER], g_ygl[(size_t)BT * DINNER];
__device__ bf16 g_h2h[BT * DMODEL],         g_h2l[BT * DMODEL];
__device__ bf16 g_ffh[(size_t)BT * DFF],    g_ffl[(size_t)BT * DFF];
__device__ bf16 g_winh[PROJ_OUT * 1024],    g_winl[PROJ_OUT * 1024];
__device__ bf16 g_woh [1024 * 2048],        g_wol [1024 * 2048];
__device__ bf16 g_w1h [4096 * 1024],        g_w1l [4096 * 1024];
__device__ bf16 g_w2h [1024 * 4096],        g_w2l [1024 * 4096];

// ---------------- math helpers ----------------
__device__ __forceinline__ float sigmoidf_(float x) { return 1.f / (1.f + __expf(-x)); }
__device__ __forceinline__ float siluf_(float x)    { return x / (1.f + __expf(-x)); }
__device__ __forceinline__ float geluf_(float x) {
    float x3 = x * x * x;
    return 0.5f * x * (1.f + tanhf(0.7978845608028654f * (x + 0.044715f * x3)));
}
__device__ __forceinline__ float softplusf_(float x) {
    return (x > 20.f) ? x : log1pf(expf(x));
}

__device__ __forceinline__ float block_reduce_sum(float v) {
    __shared__ float sh[32];
    int lane = threadIdx.x & 31, wid = threadIdx.x >> 5;
    int nwarps = blockDim.x >> 5;
    #pragma unroll
    for (int m = 16; m > 0; m >>= 1) v += __shfl_xor_sync(0xffffffffu, v, m);
    if (lane == 0) sh[wid] = v;
    __syncthreads();
    if (wid == 0) {
        v = (lane < nwarps) ? sh[lane] : 0.f;
        #pragma unroll
        for (int m = 16; m > 0; m >>= 1) v += __shfl_xor_sync(0xffffffffu, v, m);
        if (lane == 0) sh[0] = v;
    }
    __syncthreads();
    return sh[0];
}

// ---------------- low-level (sm_80-compatible only) ----------------
__device__ __forceinline__ uint32_t smem_u32(const void* p) {
    uint32_t a;
    asm("{ .reg .u64 t; cvta.to.shared.u64 t, %1; cvt.u32.u64 %0, t; }" : "=r"(a) : "l"(p));
    return a;
}
#define CP_ASYNC16(dst, src) \
    asm volatile("cp.async.cg.shared.global [%0], [%1], 16;" :: "r"((uint32_t)(dst)), "l"(src))
#define CP_COMMIT() asm volatile("cp.async.commit_group;" ::: "memory")

__device__ __forceinline__ void ldsm_x4(uint32_t* r, uint32_t addr) {
    asm volatile("ldmatrix.sync.aligned.m8n8.x4.shared.b16 {%0,%1,%2,%3}, [%4];"
                 : "=r"(r[0]), "=r"(r[1]), "=r"(r[2]), "=r"(r[3]) : "r"(addr));
}
__device__ __forceinline__ void ldsm_x2(uint32_t* r, uint32_t addr) {
    asm volatile("ldmatrix.sync.aligned.m8n8.x2.shared.b16 {%0,%1}, [%2];"
                 : "=r"(r[0]), "=r"(r[1]) : "r"(addr));
}
__device__ __forceinline__ void mma16816(float* c, const uint32_t* a, const uint32_t* b) {
    asm volatile("mma.sync.aligned.m16n8k16.row.col.f32.bf16.bf16.f32 "
                 "{%0,%1,%2,%3}, {%4,%5,%6,%7}, {%8,%9}, {%0,%1,%2,%3};"
                 : "+f"(c[0]), "+f"(c[1]), "+f"(c[2]), "+f"(c[3])
                 : "r"(a[0]), "r"(a[1]), "r"(a[2]), "r"(a[3]), "r"(b[0]), "r"(b[1]));
}

// ---------------- rmsnorm + bf16 split ----------------
__global__ void rmsnorm_split_kernel(const float* __restrict__ x, const float* __restrict__ w,
                                     bf16* __restrict__ oh, bf16* __restrict__ ol, int D) {
    int row = blockIdx.x;
    const float* xr = x + (size_t)row * D;
    float ss = 0.f;
    for (int i = threadIdx.x; i < D; i += blockDim.x) { float v = xr[i]; ss += v * v; }
    ss = block_reduce_sum(ss);
    float inv = rsqrtf(ss / (float)D + 1e-6f);
    for (int i = threadIdx.x; i < D; i += blockDim.x) {
        float v = xr[i] * inv * w[i];
        bf16 h = __float2bfloat16(v);
        oh[(size_t)row * D + i] = h;
        ol[(size_t)row * D + i] = __float2bfloat16(v - __bfloat162float(h));
    }
}

// ---------------- gated rmsnorm + split ----------------
__global__ void gated_norm_split_kernel(const float* __restrict__ proj, const float* __restrict__ scan_y,
                                        const float* __restrict__ w,
                                        bf16* __restrict__ oh, bf16* __restrict__ ol) {
    __shared__ float buf[DINNER];
    int row = blockIdx.x;
    const float* prow = proj + (size_t)row * PROJ_OUT;
    const float* sy = scan_y + (size_t)row * DINNER;
    float ss = 0.f;
    for (int i = threadIdx.x; i < DINNER; i += blockDim.x) {
        float t = sy[i] * siluf_(prow[i]);
        buf[i] = t; ss += t * t;
    }
    ss = block_reduce_sum(ss);
    float inv = rsqrtf(ss / (float)DINNER + 1e-6f);
    for (int i = threadIdx.x; i < DINNER; i += blockDim.x) {
        float v = buf[i] * inv * w[i];
        bf16 h = __float2bfloat16(v);
        oh[(size_t)row * DINNER + i] = h;
        ol[(size_t)row * DINNER + i] = __float2bfloat16(v - __bfloat162float(h));
    }
}

// ---------------- fp32 -> bf16 hi/lo split (weights) ----------------
__global__ void split_kernel(const float* __restrict__ src, bf16* __restrict__ hi,
                             bf16* __restrict__ lo, int n) {
    int i = blockIdx.x * blockDim.x + threadIdx.x;
    if (i >= n) return;
    float v = src[i];
    bf16 h = __float2bfloat16(v);
    hi[i] = h;
    lo[i] = __float2bfloat16(v - __bfloat162float(h));
}

// ---------------- causal depthwise conv + silu ----------------
__global__ void conv_silu_kernel(const float* __restrict__ proj, const float* __restrict__ conv_w,
                                 const float* __restrict__ conv_b, float* __restrict__ value) {
    int idx = blockIdx.x * blockDim.x + threadIdx.x;
    if (idx >= BT * DINNER) return;
    int c = idx & (DINNER - 1);
    int bt = idx >> 11;
    int t = bt & (TQ - 1);
    int b = bt >> 11;
    float acc = conv_b[c];
    #pragma unroll
    for (int k = 0; k < DCONV; ++k) {
        int ts = t - (DCONV - 1) + k;
        if (ts >= 0)
            acc += proj[(size_t)(b * TQ + ts) * PROJ_OUT + DINNER + c] * conv_w[c * DCONV + k];
    }
    value[(size_t)idx] = siluf_(acc);
}

// ---------------- A/dt precompute ----------------
__global__ void params_kernel(const float* __restrict__ proj, float* __restrict__ par) {
    int idx = blockIdx.x * blockDim.x + threadIdx.x;
    if (idx >= BT * NHEADS) return;
    int h = idx & (NHEADS - 1);
    int bt = idx >> 5;
    const float* prow = proj + (size_t)bt * PROJ_OUT + PARAM_OFF;
    par[idx * 2 + 0] = softplusf_(prow[2 * h]);
    par[idx * 2 + 1] = sigmoidf_(prow[2 * h + 1]);
}

// ---------------- pack B/C for vectorized scan loads ----------------
__global__ void bcpack_kernel(const float* __restrict__ proj, float* __restrict__ bcT) {
    int idx = blockIdx.x * blockDim.x + threadIdx.x;    // BT * 16
    if (idx >= BT * 16) return;
    int n = idx & 15;
    int bt = idx >> 4;
    const float* prow = proj + (size_t)bt * PROJ_OUT + BC_OFF;
    float4 v;
    v.x = prow[n];        // B0
    v.y = prow[16 + n];   // B1
    v.z = prow[32 + n];   // C0
    v.w = prow[48 + n];   // C1
    ((float4*)bcT)[bt * 16 + n] = v;
}

// ---------------- sequential SSM scan ----------------
__global__ void scan_kernel(const float* __restrict__ bcT, const float* __restrict__ par,
                            const float* __restrict__ value, float* __restrict__ scan_y) {
    int blk = blockIdx.x;
    int bh = blk >> 1;
    int b = bh >> 5;
    int h = bh & 31;
    int half = blk & 1;
    int tid = threadIdx.x;
    int p = half * 32 + (tid >> 4);
    int n = tid & 15;
    float S0 = 0.f, S1 = 0.f;
    const size_t rowbase = (size_t)b * TQ;
    const float4* bc4 = (const float4*)bcT;
    const float2* ad2 = (const float2*)par;
    float4 nbc = bc4[rowbase * 16 + n];
    float2 nad = ad2[rowbase * NHEADS + h];
    float  nu  = value[rowbase * DINNER + h * DHEAD + p];
    for (int t = 0; t < TQ; ++t) {
        float4 bcv = nbc; float2 ad = nad; float u = nu;
        if (t + 1 < TQ) {
            size_t r2 = rowbase + t + 1;
            nbc = bc4[r2 * 16 + n];
            nad = ad2[r2 * NHEADS + h];
            nu  = value[r2 * DINNER + h * DHEAD + p];
        }
        float A = ad.x, dt = ad.y;
        float dtA = dt * A;
        float du = dt * u;
        float s0n = fmaf(-dtA, S1, fmaf(bcv.x, du, S0));
        float s1n = fmaf(dt, S0, fmaf(1.f - dt * dtA, S1, dt * bcv.y * du));
        S0 = s0n; S1 = s1n;
        float y = bcv.z * s0n + bcv.w * s1n;
        y += __shfl_xor_sync(0xffffffffu, y, 8);
        y += __shfl_xor_sync(0xffffffffu, y, 4);
        y += __shfl_xor_sync(0xffffffffu, y, 2);
        y += __shfl_xor_sync(0xffffffffu, y, 1);
        if (n == 0) scan_y[(rowbase + t) * DINNER + h * DHEAD + p] = y;
    }
}

// ---------------- bf16 split-precision GEMM via mma.sync (HMMA) ----------------
// Single-pass interleaved products: per K-chunk load Ah,Al,Bh,Bl once and issue
// Ah*Bh + Ah*Bl + Al*Bh. CTA tile 128x128, BK=32, 256 threads, 2-stage cp.async.
// mode 0: C = acc ; mode 1: C = acc + bias? + res? ; mode 2: split(gelu(acc+bias)) -> Oh/Ol
#define ASTRIDE 40                  // bf16 per smem row (80B) -> conflict-free ldmatrix
#define TILEB (128 * ASTRIDE * 2)   // bytes per tile (10240)
#define STAGEB (4 * TILEB)          // bytes per stage (40960)
#define GEMM_SMEM (2 * STAGEB)      // 81920
__global__ void __launch_bounds__(256, 2)
gemm_mma(const bf16* __restrict__ Ah, const bf16* __restrict__ Al,
         const bf16* __restrict__ Bh, const bf16* __restrict__ Bl,
         const float* __restrict__ bias, const float* __restrict__ res,
         float* __restrict__ C, bf16* __restrict__ Oh, bf16* __restrict__ Ol,
         int N, int K, int mode) {
    extern __shared__ __align__(16) bf16 dsm[];
    const uint32_t s0 = smem_u32(dsm);
    const int tid = threadIdx.x, wid = tid >> 5, lane = tid & 31;
    const int row0 = blockIdx.y * 128, col0 = blockIdx.x * 128;
    const int wm = wid & 1, wn = wid >> 1;          // 2 x 4 warp grid
    const int nch = K >> 5;

    float acc[4][4][4];
    #pragma unroll
    for (int mt = 0; mt < 4; ++mt)
        #pragma unroll
        for (int nt = 0; nt < 4; ++nt)
            #pragma unroll
            for (int q = 0; q < 4; ++q) acc[mt][nt][q] = 0.f;

    // loader: each tile = 512 16B-chunks; thread covers rows lr0, lr0+64 at col lc0
    const int lr0 = tid >> 2, lc0 = tid & 3;
    const int lr1 = lr0 + 64;

    const bf16* gAh = Ah + (size_t)row0 * K + lc0 * 8;
    const bf16* gAl = Al + (size_t)row0 * K + lc0 * 8;
    const bf16* gBh = Bh + (size_t)col0 * K + lc0 * 8;
    const bf16* gBl = Bl + (size_t)col0 * K + lc0 * 8;
    const uint32_t drow0 = lr0 * 80 + lc0 * 16, drow1 = lr1 * 80 + lc0 * 16;

    #define LOAD_CHUNK(stg, k0) do {                                              \
        uint32_t _b = s0 + (stg) * STAGEB;                                        \
        CP_ASYNC16(_b + drow0,             gAh + (size_t)lr0 * K + (k0));         \
        CP_ASYNC16(_b + drow1,             gAh + (size_t)lr1 * K + (k0));         \
        CP_ASYNC16(_b + TILEB + drow0,     gAl + (size_t)lr0 * K + (k0));         \
        CP_ASYNC16(_b + TILEB + drow1,     gAl + (size_t)lr1 * K + (k0));         \
        CP_ASYNC16(_b + 2 * TILEB + drow0, gBh + (size_t)lr0 * K + (k0));         \
        CP_ASYNC16(_b + 2 * TILEB + drow1, gBh + (size_t)lr1 * K + (k0));         \
        CP_ASYNC16(_b + 3 * TILEB + drow0, gBl + (size_t)lr0 * K + (k0));         \
        CP_ASYNC16(_b + 3 * TILEB + drow1, gBl + (size_t)lr1 * K + (k0));         \
        CP_COMMIT();                                                              \
    } while (0)

    LOAD_CHUNK(0, 0);

    // ldmatrix address components (within a tile)
    const uint32_t a_row = (uint32_t)(wm * 64 + (lane & 15));
    const uint32_t a_coff = (uint32_t)((lane >> 4) * 8);
    const uint32_t b_row = (uint32_t)(wn * 32 + (lane & 7));
    const uint32_t b_coff = (uint32_t)(((lane >> 3) & 1) * 8);

    for (int ch = 0; ch < nch; ++ch) {
        const int stg = ch & 1;
        if (ch + 1 < nch) {
            LOAD_CHUNK(stg ^ 1, (ch + 1) << 5);
            asm volatile("cp.async.wait_group 1;" ::: "memory");
        } else {
            asm volatile("cp.async.wait_group 0;" ::: "memory");
        }
        __syncthreads();

        const uint32_t sb = s0 + stg * STAGEB;
        const uint32_t sAh_ = sb, sAl_ = sb + TILEB, sBh_ = sb + 2 * TILEB, sBl_ = sb + 3 * TILEB;
        #pragma unroll
        for (int ks = 0; ks < 2; ++ks) {
            const uint32_t acol = (ks * 16 + a_coff) * 2;
            const uint32_t bcol = (ks * 16 + b_coff) * 2;
            uint32_t afr[4][4], bh_[4][2], bl_[4][2];
            #pragma unroll
            for (int mt = 0; mt < 4; ++mt)
                ldsm_x4(afr[mt], sAh_ + (a_row + mt * 16) * 80 + acol);
            #pragma unroll
            for (int nt = 0; nt < 4; ++nt) {
                ldsm_x2(bh_[nt], sBh_ + (b_row + nt * 8) * 80 + bcol);
                ldsm_x2(bl_[nt], sBl_ + (b_row + nt * 8) * 80 + bcol);
            }
            #pragma unroll
            for (int mt = 0; mt < 4; ++mt)
                #pragma unroll
                for (int nt = 0; nt < 4; ++nt) {
                    mma16816(acc[mt][nt], afr[mt], bh_[nt]);
                    mma16816(acc[mt][nt], afr[mt], bl_[nt]);
                }
            #pragma unroll
            for (int mt = 0; mt < 4; ++mt)
                ldsm_x4(afr[mt], sAl_ + (a_row + mt * 16) * 80 + acol);   // reuse regs
            #pragma unroll
            for (int mt = 0; mt < 4; ++mt)
                #pragma unroll
                for (int nt = 0; nt < 4; ++nt)
                    mma16816(acc[mt][nt], afr[mt], bh_[nt]);
        }
        __syncthreads();
    }

    // epilogue
    const int er = lane >> 2, ec = (lane & 3) << 1;
    #pragma unroll
    for (int mt = 0; mt < 4; ++mt) {
        #pragma unroll
        for (int nt = 0; nt < 4; ++nt) {
            int gr = row0 + wm * 64 + mt * 16 + er;
            int gc = col0 + wn * 32 + nt * 8 + ec;
            const float* cc = acc[mt][nt];
            #pragma unroll
            for (int half = 0; half < 2; ++half) {
                int r = gr + half * 8;
                float v0 = cc[half * 2 + 0], v1 = cc[half * 2 + 1];
                if (mode == 2) {
                    v0 = geluf_(v0 + bias[gc]);
                    v1 = geluf_(v1 + bias[gc + 1]);
                    bf16 h0 = __float2bfloat16(v0), h1 = __float2bfloat16(v1);
                    size_t o = (size_t)r * N + gc;
                    Oh[o] = h0; Oh[o + 1] = h1;
                    Ol[o] = __float2bfloat16(v0 - __bfloat162float(h0));
                    Ol[o + 1] = __float2bfloat16(v1 - __bfloat162float(h1));
                } else {
                    if (bias) { v0 += bias[gc]; v1 += bias[gc + 1]; }
                    if (res) {
                        const float* rp = res + (size_t)r * N + gc;
                        v0 += rp[0]; v1 += rp[1];
                    }
                    float2 v; v.x = v0; v.y = v1;
                    *(float2*)(C + (size_t)r * N + gc) = v;
                }
            }
        }
    }
}

// ---------------- launch ----------------
extern "C" void kernel_launch(void* const* d_in, const int* in_sizes, int n_in,
                              void* d_out, int out_size) {
    const float* x       = (const float*)d_in[0];
    const float* w_in    = (const float*)d_in[1];
    const float* conv_w  = (const float*)d_in[2];
    const float* conv_b  = (const float*)d_in[3];
    const float* norm1_w = (const float*)d_in[4];
    const float* out_nw  = (const float*)d_in[5];
    const float* w_out   = (const float*)d_in[6];
    const float* norm2_w = (const float*)d_in[7];
    const float* ff_w1   = (const float*)d_in[8];
    const float* ff_b1   = (const float*)d_in[9];
    const float* ff_w2   = (const float*)d_in[10];
    const float* ff_b2   = (const float*)d_in[11];
    float* out = (float*)d_out;

    float *proj, *val, *par, *bcT, *scan, *x1;
    bf16 *h1h, *h1l, *ygh, *ygl, *h2h, *h2l, *ffh, *ffl;
    bf16 *winh, *winl, *woh, *wol, *w1h, *w1l, *w2h, *w2l;
    cudaGetSymbolAddress((void**)&proj, g_proj);
    cudaGetSymbolAddress((void**)&val,  g_val);
    cudaGetSymbolAddress((void**)&par,  g_par);
    cudaGetSymbolAddress((void**)&bcT,  g_bcT);
    cudaGetSymbolAddress((void**)&scan, g_scan);
    cudaGetSymbolAddress((void**)&x1,   g_x1);
    cudaGetSymbolAddress((void**)&h1h,  g_h1h);  cudaGetSymbolAddress((void**)&h1l, g_h1l);
    cudaGetSymbolAddress((void**)&ygh,  g_ygh);  cudaGetSymbolAddress((void**)&ygl, g_ygl);
    cudaGetSymbolAddress((void**)&h2h,  g_h2h);  cudaGetSymbolAddress((void**)&h2l, g_h2l);
    cudaGetSymbolAddress((void**)&ffh,  g_ffh);  cudaGetSymbolAddress((void**)&ffl, g_ffl);
    cudaGetSymbolAddress((void**)&winh, g_winh); cudaGetSymbolAddress((void**)&winl, g_winl);
    cudaGetSymbolAddress((void**)&woh,  g_woh);  cudaGetSymbolAddress((void**)&wol, g_wol);
    cudaGetSymbolAddress((void**)&w1h,  g_w1h);  cudaGetSymbolAddress((void**)&w1l, g_w1l);
    cudaGetSymbolAddress((void**)&w2h,  g_w2h);  cudaGetSymbolAddress((void**)&w2l, g_w2l);

    cudaFuncSetAttribute(gemm_mma, cudaFuncAttributeMaxDynamicSharedMemorySize, GEMM_SMEM);

    // weight splits (idempotent)
    split_kernel<<<(PROJ_OUT * 1024 + 255) / 256, 256>>>(w_in, winh, winl, PROJ_OUT * 1024);
    split_kernel<<<(1024 * 2048 + 255) / 256, 256>>>(w_out, woh, wol, 1024 * 2048);
    split_kernel<<<(4096 * 1024 + 255) / 256, 256>>>(ff_w1, w1h, w1l, 4096 * 1024);
    split_kernel<<<(1024 * 4096 + 255) / 256, 256>>>(ff_w2, w2h, w2l, 1024 * 4096);

    // 1. h1 = rmsnorm(x) (split)
    rmsnorm_split_kernel<<<BT, 256>>>(x, norm1_w, h1h, h1l, DMODEL);
    // 2. proj = h1 @ w_in^T  (4096 x 4224 x 1024)
    gemm_mma<<<dim3(PROJ_OUT / 128, BT / 128), 256, GEMM_SMEM>>>(h1h, h1l, winh, winl, nullptr, nullptr,
                                                      proj, nullptr, nullptr, PROJ_OUT, DMODEL, 0);
    // 3. conv + silu
    conv_silu_kernel<<<(BT * DINNER + 255) / 256, 256>>>(proj, conv_w, conv_b, val);
    // 4. A/dt + packed B/C
    params_kernel<<<(BT * NHEADS + 255) / 256, 256>>>(proj, par);
    bcpack_kernel<<<(BT * 16 + 255) / 256, 256>>>(proj, bcT);
    // 5. scan
    scan_kernel<<<2 * BQ * NHEADS, 512>>>(bcT, par, val, scan);
    // 6. yg = rmsnorm(scan * silu(gate)) (split)
    gated_norm_split_kernel<<<BT, 256>>>(proj, scan, out_nw, ygh, ygl);
    // 7. x1 = x + yg @ w_out^T  (4096 x 1024 x 2048)
    gemm_mma<<<dim3(DMODEL / 128, BT / 128), 256, GEMM_SMEM>>>(ygh, ygl, woh, wol, nullptr, x,
                                                    x1, nullptr, nullptr, DMODEL, DINNER, 1);
    // 8. h2 = rmsnorm(x1) (split)
    rmsnorm_split_kernel<<<BT, 256>>>(x1, norm2_w, h2h, h2l, DMODEL);
    // 9. ffa = split(gelu(h2 @ ff_w1^T + b1))  (4096 x 4096 x 1024)
    gemm_mma<<<dim3(DFF / 128, BT / 128), 256, GEMM_SMEM>>>(h2h, h2l, w1h, w1l, ff_b1, nullptr,
                                                 nullptr, ffh, ffl, DFF, DMODEL, 2);
    // 10. out = x1 + ffa @ ff_w2^T + b2  (4096 x 1024 x 4096)
    gemm_mma<<<dim3(DMODEL / 128, BT / 128), 256, GEMM_SMEM>>>(ffh, ffl, w2h, w2l, ff_b2, x1,
                                                    out, nullptr, nullptr, DMODEL, DFF, 1);
}